// round 11
// baseline (speedup 1.0000x reference)
#include <cuda_runtime.h>

#define N 8192
#define G 296              // kernel-1 grid (2 CTAs per SM on 148 SMs)
#define TPB 256
#define F4_PER_ROW (N / 4)               // 2048 float4 per row
#define F4_PER_THR (F4_PER_ROW / TPB)    // 8 float4 per thread per row

// Scratch (allocation-free rule: __device__ globals)
__device__ float g_partial[(size_t)G * N];   // per-CTA column partial sums (~9.7 MB)
__device__ float g_norm[N];                  // norm per row
__device__ float g_diag[N];                  // T diag per row (ts[i][i]^2)

// ---------------------------------------------------------------------------
// Kernel 1: single pass over ts (256 MB), software-pipelined.
// Double-buffered row registers: prefetch row r+G while reducing/accumulating
// row r. ONE barrier per row: warp shfl reduce -> shared -> barrier -> every
// thread sums the 8 warp partials via broadcast LDS (parity double-buffered).
// ---------------------------------------------------------------------------
__global__ __launch_bounds__(TPB, 2) void nuiv_k1(const float* __restrict__ ts,
                                                  const float* __restrict__ state) {
    __shared__ float s_sum[2][TPB / 32];
    __shared__ float s_dia[2][TPB / 32];

    const int tid  = threadIdx.x;
    const int lane = tid & 31;
    const int wid  = tid >> 5;

    const float4* ts4 = reinterpret_cast<const float4*>(ts);

    float4 acc[F4_PER_THR];
#pragma unroll
    for (int k = 0; k < F4_PER_THR; k++) acc[k] = make_float4(0.f, 0.f, 0.f, 0.f);

    int row = blockIdx.x;
    if (row < N) {
        // preload first row
        float4 vc[F4_PER_THR];
        {
            const float4* rp = ts4 + (size_t)row * F4_PER_ROW;
#pragma unroll
            for (int k = 0; k < F4_PER_THR; k++) vc[k] = rp[tid + k * TPB];
        }

        int p = 0;
        for (; row < N; row += G, p ^= 1) {
            // ---- prefetch next row (loads issue before any barrier/wait) ----
            float4 vn[F4_PER_THR];
            if (row + G < N) {
                const float4* rpn = ts4 + (size_t)(row + G) * F4_PER_ROW;
#pragma unroll
                for (int k = 0; k < F4_PER_THR; k++) vn[k] = rpn[tid + k * TPB];
            }

            // ---- consume current row: square in place, sumsq + diag ----
            float sum = 0.f, diag2 = 0.f;
#pragma unroll
            for (int k = 0; k < F4_PER_THR; k++) {
                float4 x = vc[k];
                x.x *= x.x; x.y *= x.y; x.z *= x.z; x.w *= x.w;   // T = ts^2
                vc[k] = x;
                sum += (x.x + x.y) + (x.z + x.w);
                const int base = 4 * (tid + k * TPB);
                if (row >= base && row < base + 4) {
                    const int r = row - base;
                    diag2 = (r == 0) ? x.x : (r == 1) ? x.y : (r == 2) ? x.z : x.w;
                }
            }

            // ---- warp reduce, then ONE barrier + broadcast combine ----
#pragma unroll
            for (int off = 16; off > 0; off >>= 1) {
                sum   += __shfl_xor_sync(0xFFFFFFFFu, sum,   off);
                diag2 += __shfl_xor_sync(0xFFFFFFFFu, diag2, off);
            }
            if (lane == 0) { s_sum[p][wid] = sum; s_dia[p][wid] = diag2; }
            __syncthreads();

            float rowsum = 0.f, dg = 0.f;
#pragma unroll
            for (int w = 0; w < TPB / 32; w++) {
                rowsum += s_sum[p][w];
                dg     += s_dia[p][w];
            }

            const float nrm = fminf(dg / (rowsum - dg), 1.0f);
            const float w   = nrm * __ldg(state + 3 * row + 2);   // V[row]
            if (tid == 0) { g_norm[row] = nrm; g_diag[row] = dg; }

            // ---- accumulate column partials in registers ----
#pragma unroll
            for (int k = 0; k < F4_PER_THR; k++) {
                acc[k].x = fmaf(w, vc[k].x, acc[k].x);
                acc[k].y = fmaf(w, vc[k].y, acc[k].y);
                acc[k].z = fmaf(w, vc[k].z, acc[k].z);
                acc[k].w = fmaf(w, vc[k].w, acc[k].w);
            }

            // rotate buffers
#pragma unroll
            for (int k = 0; k < F4_PER_THR; k++) vc[k] = vn[k];
        }
    }

    float4* pp = reinterpret_cast<float4*>(g_partial + (size_t)blockIdx.x * N);
#pragma unroll
    for (int k = 0; k < F4_PER_THR; k++) pp[tid + k * TPB] = acc[k];
}

// ---------------------------------------------------------------------------
// Kernel 2: 1024 blocks x 256 threads; each block owns 8 columns, 32 threads
// per column. Each thread fully unrolls its 9-10 independent partial loads
// (MLP ~10), then 2 shfl levels + tiny shared combine reduce the g-dimension.
// ---------------------------------------------------------------------------
#define K2_GRID (N / 8)   // 1024

__global__ __launch_bounds__(TPB) void nuiv_k2(const float* __restrict__ state,
                                               const float* __restrict__ betas,
                                               const float* __restrict__ deltas,
                                               const float* __restrict__ cs,
                                               const float* __restrict__ ps,
                                               float* __restrict__ out) {
    __shared__ float sh[TPB / 32][8];

    const int t     = threadIdx.x;
    const int col   = t & 7;          // column within block (0..7)
    const int gslot = t >> 3;         // 0..31
    const int wrp   = t >> 5;
    const int j     = blockIdx.x * 8 + col;

    // G = 296 = 32*9 + 8: every gslot does 9 loads, gslot<8 does one extra.
    float a[9];
#pragma unroll
    for (int i = 0; i < 9; i++)
        a[i] = g_partial[(size_t)(gslot + 32 * i) * N + j];
    float extra = (gslot < 8) ? g_partial[(size_t)(gslot + 288) * N + j] : 0.f;

    float s = ((a[0] + a[1]) + (a[2] + a[3])) +
              ((a[4] + a[5]) + (a[6] + a[7])) + (a[8] + extra);

    // reduce across gslot within warp (gslot bits 0,1 of warp-local slot)
    s += __shfl_xor_sync(0xFFFFFFFFu, s, 8);
    s += __shfl_xor_sync(0xFFFFFFFFu, s, 16);
    if ((t & 31) < 8) sh[wrp][col] = s;
    __syncthreads();

    if (t < 8) {
        float colsum = 0.f;
#pragma unroll
        for (int w = 0; w < TPB / 32; w++) colsum += sh[w][t];

        const int jj = blockIdx.x * 8 + t;
        const float diag = g_diag[jj];
        const float nrm  = g_norm[jj];

        const float U = state[3 * jj + 0];
        const float I = state[3 * jj + 1];
        const float V = state[3 * jj + 2];
        const float b = betas[jj],  b2 = b * b;
        const float d = deltas[jj], d2 = d * d;
        const float c = cs[jj],     c2 = c * c;
        const float p = ps[jj],     p2 = p * p;

        const float bUV      = b2 * U * V;
        const float coupling = colsum - nrm * diag * V;   // remove i==j term
        const float dV       = p2 * I - c2 * V - diag + coupling;

        out[3 * jj + 0] = -bUV;
        out[3 * jj + 1] = bUV - d2 * I;
        out[3 * jj + 2] = dV;
    }
}

extern "C" void kernel_launch(void* const* d_in, const int* in_sizes, int n_in,
                              void* d_out, int out_size) {
    // inputs: 0=t, 1=state(3N), 2=betas, 3=deltas, 4=cs, 5=ps, 6=ts(N*N)
    const float* state  = (const float*)d_in[1];
    const float* betas  = (const float*)d_in[2];
    const float* deltas = (const float*)d_in[3];
    const float* cs     = (const float*)d_in[4];
    const float* ps     = (const float*)d_in[5];
    const float* ts     = (const float*)d_in[6];
    float* out = (float*)d_out;

    nuiv_k1<<<G, TPB>>>(ts, state);
    nuiv_k2<<<K2_GRID, TPB>>>(state, betas, deltas, cs, ps, out);
}

// round 12
// speedup vs baseline: 1.0025x; 1.0025x over previous
#include <cuda_runtime.h>

#define N 8192
#define G 296              // kernel-1 grid (2 CTAs per SM on 148 SMs)
#define TPB 256
#define F4_PER_ROW (N / 4)               // 2048 float4 per row
#define F4_PER_THR (F4_PER_ROW / TPB)    // 8 float4 per thread per row

// Scratch (allocation-free rule: __device__ globals)
__device__ float g_partial[(size_t)G * N];   // per-CTA column partial sums (~9.7 MB)
__device__ float g_norm[N];                  // norm per row
__device__ float g_diag[N];                  // T diag per row (ts[i][i]^2)

// ---------------------------------------------------------------------------
// Kernel 1: single pass over ts (256 MB), software-pipelined.
// Double-buffered row registers: prefetch row r+G while reducing/accumulating
// row r. ONE barrier per row: warp shfl reduce -> shared -> barrier -> every
// thread sums the 8 warp partials via broadcast LDS (parity double-buffered).
// ---------------------------------------------------------------------------
__global__ __launch_bounds__(TPB, 2) void nuiv_k1(const float* __restrict__ ts,
                                                  const float* __restrict__ state) {
    __shared__ float s_sum[2][TPB / 32];
    __shared__ float s_dia[2][TPB / 32];

    const int tid  = threadIdx.x;
    const int lane = tid & 31;
    const int wid  = tid >> 5;

    const float4* ts4 = reinterpret_cast<const float4*>(ts);

    float4 acc[F4_PER_THR];
#pragma unroll
    for (int k = 0; k < F4_PER_THR; k++) acc[k] = make_float4(0.f, 0.f, 0.f, 0.f);

    int row = blockIdx.x;
    if (row < N) {
        // preload first row
        float4 vc[F4_PER_THR];
        {
            const float4* rp = ts4 + (size_t)row * F4_PER_ROW;
#pragma unroll
            for (int k = 0; k < F4_PER_THR; k++) vc[k] = rp[tid + k * TPB];
        }

        int p = 0;
        for (; row < N; row += G, p ^= 1) {
            // ---- prefetch next row (loads issue before any barrier/wait) ----
            float4 vn[F4_PER_THR];
            if (row + G < N) {
                const float4* rpn = ts4 + (size_t)(row + G) * F4_PER_ROW;
#pragma unroll
                for (int k = 0; k < F4_PER_THR; k++) vn[k] = rpn[tid + k * TPB];
            }

            // ---- consume current row: square in place, sumsq + diag ----
            float sum = 0.f, diag2 = 0.f;
#pragma unroll
            for (int k = 0; k < F4_PER_THR; k++) {
                float4 x = vc[k];
                x.x *= x.x; x.y *= x.y; x.z *= x.z; x.w *= x.w;   // T = ts^2
                vc[k] = x;
                sum += (x.x + x.y) + (x.z + x.w);
                const int base = 4 * (tid + k * TPB);
                if (row >= base && row < base + 4) {
                    const int r = row - base;
                    diag2 = (r == 0) ? x.x : (r == 1) ? x.y : (r == 2) ? x.z : x.w;
                }
            }

            // ---- warp reduce, then ONE barrier + broadcast combine ----
#pragma unroll
            for (int off = 16; off > 0; off >>= 1) {
                sum   += __shfl_xor_sync(0xFFFFFFFFu, sum,   off);
                diag2 += __shfl_xor_sync(0xFFFFFFFFu, diag2, off);
            }
            if (lane == 0) { s_sum[p][wid] = sum; s_dia[p][wid] = diag2; }
            __syncthreads();

            float rowsum = 0.f, dg = 0.f;
#pragma unroll
            for (int w = 0; w < TPB / 32; w++) {
                rowsum += s_sum[p][w];
                dg     += s_dia[p][w];
            }

            const float nrm = fminf(dg / (rowsum - dg), 1.0f);
            const float w   = nrm * __ldg(state + 3 * row + 2);   // V[row]
            if (tid == 0) { g_norm[row] = nrm; g_diag[row] = dg; }

            // ---- accumulate column partials in registers ----
#pragma unroll
            for (int k = 0; k < F4_PER_THR; k++) {
                acc[k].x = fmaf(w, vc[k].x, acc[k].x);
                acc[k].y = fmaf(w, vc[k].y, acc[k].y);
                acc[k].z = fmaf(w, vc[k].z, acc[k].z);
                acc[k].w = fmaf(w, vc[k].w, acc[k].w);
            }

            // rotate buffers
#pragma unroll
            for (int k = 0; k < F4_PER_THR; k++) vc[k] = vn[k];
        }
    }

    float4* pp = reinterpret_cast<float4*>(g_partial + (size_t)blockIdx.x * N);
#pragma unroll
    for (int k = 0; k < F4_PER_THR; k++) pp[tid + k * TPB] = acc[k];
}

// ---------------------------------------------------------------------------
// Kernel 2: 1024 blocks x 256 threads; each block owns 8 columns, 32 threads
// per column. Each thread fully unrolls its 9-10 independent partial loads
// (MLP ~10), then 2 shfl levels + tiny shared combine reduce the g-dimension.
// ---------------------------------------------------------------------------
#define K2_GRID (N / 8)   // 1024

__global__ __launch_bounds__(TPB) void nuiv_k2(const float* __restrict__ state,
                                               const float* __restrict__ betas,
                                               const float* __restrict__ deltas,
                                               const float* __restrict__ cs,
                                               const float* __restrict__ ps,
                                               float* __restrict__ out) {
    __shared__ float sh[TPB / 32][8];

    const int t     = threadIdx.x;
    const int col   = t & 7;          // column within block (0..7)
    const int gslot = t >> 3;         // 0..31
    const int wrp   = t >> 5;
    const int j     = blockIdx.x * 8 + col;

    // G = 296 = 32*9 + 8: every gslot does 9 loads, gslot<8 does one extra.
    float a[9];
#pragma unroll
    for (int i = 0; i < 9; i++)
        a[i] = g_partial[(size_t)(gslot + 32 * i) * N + j];
    float extra = (gslot < 8) ? g_partial[(size_t)(gslot + 288) * N + j] : 0.f;

    float s = ((a[0] + a[1]) + (a[2] + a[3])) +
              ((a[4] + a[5]) + (a[6] + a[7])) + (a[8] + extra);

    // reduce across gslot within warp (gslot bits 0,1 of warp-local slot)
    s += __shfl_xor_sync(0xFFFFFFFFu, s, 8);
    s += __shfl_xor_sync(0xFFFFFFFFu, s, 16);
    if ((t & 31) < 8) sh[wrp][col] = s;
    __syncthreads();

    if (t < 8) {
        float colsum = 0.f;
#pragma unroll
        for (int w = 0; w < TPB / 32; w++) colsum += sh[w][t];

        const int jj = blockIdx.x * 8 + t;
        const float diag = g_diag[jj];
        const float nrm  = g_norm[jj];

        const float U = state[3 * jj + 0];
        const float I = state[3 * jj + 1];
        const float V = state[3 * jj + 2];
        const float b = betas[jj],  b2 = b * b;
        const float d = deltas[jj], d2 = d * d;
        const float c = cs[jj],     c2 = c * c;
        const float p = ps[jj],     p2 = p * p;

        const float bUV      = b2 * U * V;
        const float coupling = colsum - nrm * diag * V;   // remove i==j term
        const float dV       = p2 * I - c2 * V - diag + coupling;

        out[3 * jj + 0] = -bUV;
        out[3 * jj + 1] = bUV - d2 * I;
        out[3 * jj + 2] = dV;
    }
}

extern "C" void kernel_launch(void* const* d_in, const int* in_sizes, int n_in,
                              void* d_out, int out_size) {
    // inputs: 0=t, 1=state(3N), 2=betas, 3=deltas, 4=cs, 5=ps, 6=ts(N*N)
    const float* state  = (const float*)d_in[1];
    const float* betas  = (const float*)d_in[2];
    const float* deltas = (const float*)d_in[3];
    const float* cs     = (const float*)d_in[4];
    const float* ps     = (const float*)d_in[5];
    const float* ts     = (const float*)d_in[6];
    float* out = (float*)d_out;

    nuiv_k1<<<G, TPB>>>(ts, state);
    nuiv_k2<<<K2_GRID, TPB>>>(state, betas, deltas, cs, ps, out);
}